// round 15
// baseline (speedup 1.0000x reference)
#include <cuda_runtime.h>
#include <math.h>
#include <stdint.h>

// ---------------- problem constants ----------------
#define BB     2
#define TT     1024
#define DD     768
#define NHH    12
#define HN     512          // head dim N
#define HH     6144         // NH*N
#define LL     4
#define VOCABN 32000
#define KKEEP  921          // int(6144*0.15)
#define NTOK   (BB*TT)      // 2048

typedef unsigned long long ull;

// ---------------- packed f32x2 helpers (SASS FFMA2 path) ----------------
#define FMA2(d, a, b) \
    asm("fma.rn.f32x2 %0, %1, %2, %0;" : "+l"(d) : "l"(a), "l"(b))
#define ADD2(d, s) \
    asm("add.rn.f32x2 %0, %0, %1;" : "+l"(d) : "l"(s))
#define PACK_DUP(d, x) \
    asm("mov.b64 %0, {%1, %1};" : "=l"(d) : "f"(x))
#define UNPACK2(lo, hi, v) \
    asm("mov.b64 {%0, %1}, %2;" : "=f"(lo), "=f"(hi) : "l"(v))

// ---------------- scratch (device globals; no allocs allowed) ----------------
__device__ float g_x   [(size_t)NTOK*DD];
__device__ float g_q   [(size_t)NTOK*HH];   // encoder q out; later flat y
__device__ float g_v   [(size_t)NTOK*HH];   // encoder v out
__device__ float g_qr  [(size_t)BB*NHH*TT*HN];
__device__ float g_vt  [(size_t)BB*NHH*TT*HN];
__device__ float g_att [(size_t)BB*NHH*TT*TT];   // 100 MB scores/probs
__device__ float g_ydec[(size_t)NTOK*DD];
__device__ float g_We  [(size_t)DD*HH];
__device__ float g_Wev [(size_t)DD*HH];
__device__ float g_cos [(size_t)TT*HN];
__device__ float g_sin [(size_t)TT*HN];

// ---------------- reductions ----------------
__device__ __forceinline__ float warpReduceMax(float v){
#pragma unroll
    for (int o = 16; o > 0; o >>= 1) v = fmaxf(v, __shfl_down_sync(0xffffffffu, v, o));
    return v;
}
__device__ __forceinline__ double warpReduceSumD(double v){
#pragma unroll
    for (int o = 16; o > 0; o >>= 1) v += __shfl_down_sync(0xffffffffu, v, o);
    return v;
}
__device__ __forceinline__ double blockReduceSumD(double v, double* shm){
    int lane = threadIdx.x & 31, warp = threadIdx.x >> 5;
    v = warpReduceSumD(v);
    if (lane == 0) shm[warp] = v;
    __syncthreads();
    if (warp == 0) {
        v = (lane < ((blockDim.x + 31) >> 5)) ? shm[lane] : 0.0;
        v = warpReduceSumD(v);
        if (lane == 0) shm[0] = v;
    }
    __syncthreads();
    double r = shm[0];
    __syncthreads();
    return r;
}
__device__ __forceinline__ float blockReduceMax(float v, float* shm){
    int lane = threadIdx.x & 31, warp = threadIdx.x >> 5;
    v = warpReduceMax(v);
    if (lane == 0) shm[warp] = v;
    __syncthreads();
    if (warp == 0) {
        v = (lane < ((blockDim.x + 31) >> 5)) ? shm[lane] : -INFINITY;
        v = warpReduceMax(v);
        if (lane == 0) shm[0] = v;
    }
    __syncthreads();
    float r = shm[0];
    __syncthreads();
    return r;
}

// ---------------- fp32 chunk GEMMs (frozen numerics; layers 0-2 + encoders) --
// NUMERICS CONTRACT (R10): ascending k-chunks of 32; fresh-zero serial
// ascending FFMA(rn) chain per chunk; one rn merge per chunk. AT the scalar
// fp32 issue-rate roofline (~39 TF/s) — do not touch.
#define BM 64
#define BN 64
#define BK 32
#define GPAD 4

__global__ __launch_bounds__(64) void gemm_nn_chunk_kernel(
    const float* __restrict__ A, const float* __restrict__ B,
    float* __restrict__ C, const float* __restrict__ bias,
    int M, int N, int K,
    long long sA, long long sB, long long sC, int kLimit, int pvMode)
{
    const int z = blockIdx.z;
    A += (size_t)z * sA;
    B += (size_t)z * sB;
    int ldC = N;
    if (pvMode) { C += (size_t)(z / NHH) * TT * HH + (size_t)(z % NHH) * HN; ldC = HH; }
    else        { C += (size_t)z * sC; }
    const int bx = blockIdx.x, by = blockIdx.y;
    const int row0 = by * BM, col0 = bx * BN;
    __shared__ __align__(16) float As[BK][BM + GPAD];
    __shared__ __align__(16) float Bs[BK][BN + GPAD];
    const int tid = threadIdx.x;
    const int tx = tid & 7, ty = tid >> 3;
    ull acc2[8][4];
#pragma unroll
    for (int i = 0; i < 8; i++)
#pragma unroll
        for (int j = 0; j < 4; j++) acc2[i][j] = 0ULL;

    int kEnd = K;
    if (kLimit) { int lim = (by + 1) * BM; if (lim < kEnd) kEnd = lim; }

    for (int k0 = 0; k0 < kEnd; k0 += BK) {
#pragma unroll
        for (int e = tid; e < (BM * BK) / 4; e += 64) {
            int r = e >> 3, c4 = (e & 7) * 4;
            float4 v = *reinterpret_cast<const float4*>(&A[(size_t)(row0 + r) * K + k0 + c4]);
            As[c4 + 0][r] = v.x; As[c4 + 1][r] = v.y;
            As[c4 + 2][r] = v.z; As[c4 + 3][r] = v.w;
        }
#pragma unroll
        for (int e = tid; e < (BK * BN) / 4; e += 64) {
            int r = e >> 4, c4 = (e & 15) * 4;
            *reinterpret_cast<float4*>(&Bs[r][c4]) =
                *reinterpret_cast<const float4*>(&B[(size_t)(k0 + r) * N + col0 + c4]);
        }
        __syncthreads();

        ull s2[8][4];
#pragma unroll
        for (int i = 0; i < 8; i++)
#pragma unroll
            for (int j = 0; j < 4; j++) s2[i][j] = 0ULL;
#pragma unroll 4
        for (int kk = 0; kk < BK; kk++) {
            float a[8];
            *reinterpret_cast<float4*>(&a[0]) = *reinterpret_cast<const float4*>(&As[kk][ty * 8]);
            *reinterpret_cast<float4*>(&a[4]) = *reinterpret_cast<const float4*>(&As[kk][ty * 8 + 4]);
            const ull* brow = reinterpret_cast<const ull*>(&Bs[kk][tx * 8]);
            ull b2[4] = {brow[0], brow[1], brow[2], brow[3]};
            ull a2[8];
#pragma unroll
            for (int i = 0; i < 8; i++) PACK_DUP(a2[i], a[i]);
#pragma unroll
            for (int i = 0; i < 8; i++)
#pragma unroll
                for (int j = 0; j < 4; j++) FMA2(s2[i][j], a2[i], b2[j]);
        }
#pragma unroll
        for (int i = 0; i < 8; i++)
#pragma unroll
            for (int j = 0; j < 4; j++) ADD2(acc2[i][j], s2[i][j]);
        __syncthreads();
    }

    float bv[8];
#pragma unroll
    for (int j = 0; j < 8; j++) bv[j] = bias ? bias[col0 + tx * 8 + j] : 0.f;
#pragma unroll
    for (int i = 0; i < 8; i++) {
        float o[8];
#pragma unroll
        for (int j = 0; j < 4; j++) UNPACK2(o[2 * j], o[2 * j + 1], acc2[i][j]);
#pragma unroll
        for (int j = 0; j < 8; j++) o[j] = __fadd_rn(o[j], bv[j]);
        float* Crow = &C[(size_t)(row0 + ty * 8 + i) * ldC + col0 + tx * 8];
        *reinterpret_cast<float4*>(Crow)     = *reinterpret_cast<float4*>(&o[0]);
        *reinterpret_cast<float4*>(Crow + 4) = *reinterpret_cast<float4*>(&o[4]);
    }
}

__global__ __launch_bounds__(64) void gemm_nt_chunk_kernel(
    const float* __restrict__ A, const float* __restrict__ B,
    float* __restrict__ C,
    int M, int N, int K, float divisor,
    long long sA, long long sB, long long sC, int causal)
{
    const int bx = blockIdx.x, by = blockIdx.y;
    if (causal && bx > by) return;
    A += (size_t)blockIdx.z * sA;
    B += (size_t)blockIdx.z * sB;
    C += (size_t)blockIdx.z * sC;
    const int row0 = by * BM, col0 = bx * BN;
    __shared__ __align__(16) float As[BK][BM + GPAD];
    __shared__ __align__(16) float Bs[BK][BN + GPAD];
    const int tid = threadIdx.x;
    const int tx = tid & 7, ty = tid >> 3;
    ull acc2[8][4];
#pragma unroll
    for (int i = 0; i < 8; i++)
#pragma unroll
        for (int j = 0; j < 4; j++) acc2[i][j] = 0ULL;

    for (int k0 = 0; k0 < K; k0 += BK) {
#pragma unroll
        for (int e = tid; e < (BM * BK) / 4; e += 64) {
            int r = e >> 3, c4 = (e & 7) * 4;
            float4 v = *reinterpret_cast<const float4*>(&A[(size_t)(row0 + r) * K + k0 + c4]);
            As[c4 + 0][r] = v.x; As[c4 + 1][r] = v.y;
            As[c4 + 2][r] = v.z; As[c4 + 3][r] = v.w;
        }
#pragma unroll
        for (int e = tid; e < (BN * BK) / 4; e += 64) {
            int c = e >> 3, k4 = (e & 7) * 4;
            float4 v = *reinterpret_cast<const float4*>(&B[(size_t)(col0 + c) * K + k0 + k4]);
            Bs[k4 + 0][c] = v.x; Bs[k4 + 1][c] = v.y;
            Bs[k4 + 2][c] = v.z; Bs[k4 + 3][c] = v.w;
        }
        __syncthreads();

        ull s2[8][4];
#pragma unroll
        for (int i = 0; i < 8; i++)
#pragma unroll
            for (int j = 0; j < 4; j++) s2[i][j] = 0ULL;
#pragma unroll 4
        for (int kk = 0; kk < BK; kk++) {
            float a[8];
            *reinterpret_cast<float4*>(&a[0]) = *reinterpret_cast<const float4*>(&As[kk][ty * 8]);
            *reinterpret_cast<float4*>(&a[4]) = *reinterpret_cast<const float4*>(&As[kk][ty * 8 + 4]);
            const ull* brow = reinterpret_cast<const ull*>(&Bs[kk][tx * 8]);
            ull b2[4] = {brow[0], brow[1], brow[2], brow[3]};
            ull a2[8];
#pragma unroll
            for (int i = 0; i < 8; i++) PACK_DUP(a2[i], a[i]);
#pragma unroll
            for (int i = 0; i < 8; i++)
#pragma unroll
                for (int j = 0; j < 4; j++) FMA2(s2[i][j], a2[i], b2[j]);
        }
#pragma unroll
        for (int i = 0; i < 8; i++)
#pragma unroll
            for (int j = 0; j < 4; j++) ADD2(acc2[i][j], s2[i][j]);
        __syncthreads();
    }
#pragma unroll
    for (int i = 0; i < 8; i++) {
        float o[8];
#pragma unroll
        for (int j = 0; j < 4; j++) UNPACK2(o[2 * j], o[2 * j + 1], acc2[i][j]);
#pragma unroll
        for (int j = 0; j < 8; j++) o[j] = __fdiv_rn(o[j], divisor);
        float* Crow = &C[(size_t)(row0 + ty * 8 + i) * N + col0 + tx * 8];
        *reinterpret_cast<float4*>(Crow)     = *reinterpret_cast<float4*>(&o[0]);
        *reinterpret_cast<float4*>(Crow + 4) = *reinterpret_cast<float4*>(&o[4]);
    }
}

// ---------------- tf32 mma.sync GEMMs (smooth path: layer 3 attn + LM head) --
// 256 threads, 128x128 block tile, warp tile 32x64. Inputs converted to tf32
// ONCE at smem fill (bit-identical to converting at fragment load).
#define LBM 128
#define LBN 128
#define LBK 16
#define LPAD 8

__device__ __forceinline__ uint32_t f2tf32(float x){
    uint32_t u;
    asm("cvt.rna.tf32.f32 %0, %1;" : "=r"(u) : "f"(x));
    return u;
}

// C[M,N] = (A[M,K] * B[N,K]^T) (/divisor). causal: skip tiles above diagonal.
__global__ __launch_bounds__(256) void tf32_nt_kernel(
    const float* __restrict__ A, const float* __restrict__ B,
    float* __restrict__ C, int M, int N, int K,
    float divisor, int useDiv,
    long long sA, long long sB, long long sC, int causal)
{
    const int bx = blockIdx.x, by = blockIdx.y;
    if (causal && bx > by) return;
    const int row0 = by * LBM, col0 = bx * LBN;
    A += (size_t)blockIdx.z * sA;
    B += (size_t)blockIdx.z * sB;
    C += (size_t)blockIdx.z * sC;
    __shared__ __align__(16) uint32_t As[LBK][LBM + LPAD];
    __shared__ __align__(16) uint32_t Bs[LBK][LBN + LPAD];
    const int tid = threadIdx.x;
    const int warp = tid >> 5, lane = tid & 31;
    const int wm = (warp >> 1) * 32, wn = (warp & 1) * 64;
    const int gid = lane >> 2, tig = lane & 3;

    float c[2][8][4];
#pragma unroll
    for (int mi = 0; mi < 2; mi++)
#pragma unroll
        for (int ni = 0; ni < 8; ni++)
#pragma unroll
            for (int r = 0; r < 4; r++) c[mi][ni][r] = 0.f;

    for (int k0 = 0; k0 < K; k0 += LBK) {
#pragma unroll
        for (int e = tid; e < (LBM * LBK) / 4; e += 256) {
            int r = e >> 2, c4 = (e & 3) * 4;
            float4 v = *reinterpret_cast<const float4*>(&A[(size_t)(row0 + r) * K + k0 + c4]);
            As[c4 + 0][r] = f2tf32(v.x); As[c4 + 1][r] = f2tf32(v.y);
            As[c4 + 2][r] = f2tf32(v.z); As[c4 + 3][r] = f2tf32(v.w);
        }
#pragma unroll
        for (int e = tid; e < (LBN * LBK) / 4; e += 256) {
            int n = e >> 2, k4 = (e & 3) * 4;
            float4 v = *reinterpret_cast<const float4*>(&B[(size_t)(col0 + n) * K + k0 + k4]);
            Bs[k4 + 0][n] = f2tf32(v.x); Bs[k4 + 1][n] = f2tf32(v.y);
            Bs[k4 + 2][n] = f2tf32(v.z); Bs[k4 + 3][n] = f2tf32(v.w);
        }
        __syncthreads();

#pragma unroll
        for (int ks = 0; ks < LBK; ks += 8) {
            uint32_t af[2][4];
#pragma unroll
            for (int mi = 0; mi < 2; mi++) {
                int m0 = wm + mi * 16;
                af[mi][0] = As[ks + tig]    [m0 + gid];
                af[mi][1] = As[ks + tig]    [m0 + gid + 8];
                af[mi][2] = As[ks + tig + 4][m0 + gid];
                af[mi][3] = As[ks + tig + 4][m0 + gid + 8];
            }
            uint32_t bf[8][2];
#pragma unroll
            for (int ni = 0; ni < 8; ni++) {
                int n0 = wn + ni * 8;
                bf[ni][0] = Bs[ks + tig]    [n0 + gid];
                bf[ni][1] = Bs[ks + tig + 4][n0 + gid];
            }
#pragma unroll
            for (int mi = 0; mi < 2; mi++)
#pragma unroll
                for (int ni = 0; ni < 8; ni++) {
                    asm volatile(
                        "mma.sync.aligned.m16n8k8.row.col.f32.tf32.tf32.f32 "
                        "{%0,%1,%2,%3}, {%4,%5,%6,%7}, {%8,%9}, {%0,%1,%2,%3};"
                        : "+f"(c[mi][ni][0]), "+f"(c[mi][ni][1]),
                          "+f"(c[mi][ni][2]), "+f"(c[mi][ni][3])
                        : "r"(af[mi][0]), "r"(af[mi][1]), "r"(af[mi][2]), "r"(af[mi][3]),
                          "r"(bf[ni][0]), "r"(bf[ni][1]));
                }
        }
        __syncthreads();
    }

#pragma unroll
    for (int mi = 0; mi < 2; mi++)
#pragma unroll
        for (int ni = 0; ni < 8; ni++) {
            int r = row0 + wm + mi * 16 + gid;
            int cc = col0 + wn + ni * 8 + 2 * tig;
            float v0 = c[mi][ni][0], v1 = c[mi][ni][1];
            float v2 = c[mi][ni][2], v3 = c[mi][ni][3];
            if (useDiv) {
                v0 = __fdiv_rn(v0, divisor); v1 = __fdiv_rn(v1, divisor);
                v2 = __fdiv_rn(v2, divisor); v3 = __fdiv_rn(v3, divisor);
            }
            *reinterpret_cast<float2*>(&C[(size_t)r * N + cc])       = make_float2(v0, v1);
            *reinterpret_cast<float2*>(&C[(size_t)(r + 8) * N + cc]) = make_float2(v2, v3);
        }
}

// C[M,N] = A[M,K] * B[K,N] (+bias). kLimit: K limited to row0+LBM (causal PV;
// extra P terms are exact zeros -> bit-exact). pvMode: flat attn-output write.
__global__ __launch_bounds__(256) void tf32_nn_kernel(
    const float* __restrict__ A, const float* __restrict__ B,
    float* __restrict__ C, const float* __restrict__ bias,
    int M, int N, int K,
    long long sA, long long sB, long long sC, int kLimit, int pvMode)
{
    const int z = blockIdx.z;
    A += (size_t)z * sA;
    B += (size_t)z * sB;
    int ldC = N;
    if (pvMode) { C += (size_t)(z / NHH) * TT * HH + (size_t)(z % NHH) * HN; ldC = HH; }
    else        { C += (size_t)z * sC; }
    const int bx = blockIdx.x, by = blockIdx.y;
    const int row0 = by * LBM, col0 = bx * LBN;
    __shared__ __align__(16) uint32_t As[LBK][LBM + LPAD];
    __shared__ __align__(16) uint32_t Bs[LBK][LBN + LPAD];
    const int tid = threadIdx.x;
    const int warp = tid >> 5, lane = tid & 31;
    const int wm = (warp >> 1) * 32, wn = (warp & 1) * 64;
    const int gid = lane >> 2, tig = lane & 3;

    float c[2][8][4];
#pragma unroll
    for (int mi = 0; mi < 2; mi++)
#pragma unroll
        for (int ni = 0; ni < 8; ni++)
#pragma unroll
            for (int r = 0; r < 4; r++) c[mi][ni][r] = 0.f;

    int kEnd = K;
    if (kLimit) { int lim = row0 + LBM; if (lim < kEnd) kEnd = lim; }

    for (int k0 = 0; k0 < kEnd; k0 += LBK) {
#pragma unroll
        for (int e = tid; e < (LBM * LBK) / 4; e += 256) {
            int r = e >> 2, c4 = (e & 3) * 4;
            float4 v = *reinterpret_cast<const float4*>(&A[(size_t)(row0 + r) * K + k0 + c4]);
            As[c4 + 0][r] = f2tf32(v.x); As[c4 + 1][r] = f2tf32(v.y);
            As[c4 + 2][r] = f2tf32(v.z); As[c4 + 3][r] = f2tf32(v.w);
        }
#pragma unroll
        for (int e = tid; e < (LBK * LBN) / 4; e += 256) {
            int k = e >> 5, c4 = (e & 31) * 4;
            float4 v = *reinterpret_cast<const float4*>(&B[(size_t)(k0 + k) * N + col0 + c4]);
            Bs[k][c4 + 0] = f2tf32(v.x); Bs[k][c4 + 1] = f2tf32(v.y);
            Bs[k][c4 + 2] = f2tf32(v.z); Bs[k][c4 + 3] = f2tf32(v.w);
        }
        __syncthreads();

#pragma unroll
        for (int ks = 0; ks < LBK; ks += 8) {
            uint32_t af[2][4];
#pragma unroll
            for (int mi = 0; mi < 2; mi++) {
                int m0 = wm + mi * 16;
                af[mi][0] = As[ks + tig]    [m0 + gid];
                af[mi][1] = As[ks + tig]    [m0 + gid + 8];
                af[mi][2] = As[ks + tig + 4][m0 + gid];
                af[mi][3] = As[ks + tig + 4][m0 + gid + 8];
            }
            uint32_t bf[8][2];
#pragma unroll
            for (int ni = 0; ni < 8; ni++) {
                int n0 = wn + ni * 8;
                bf[ni][0] = Bs[ks + tig]    [n0 + gid];
                bf[ni][1] = Bs[ks + tig + 4][n0 + gid];
            }
#pragma unroll
            for (int mi = 0; mi < 2; mi++)
#pragma unroll
                for (int ni = 0; ni < 8; ni++) {
                    asm volatile(
                        "mma.sync.aligned.m16n8k8.row.col.f32.tf32.tf32.f32 "
                        "{%0,%1,%2,%3}, {%4,%5,%6,%7}, {%8,%9}, {%0,%1,%2,%3};"
                        : "+f"(c[mi][ni][0]), "+f"(c[mi][ni][1]),
                          "+f"(c[mi][ni][2]), "+f"(c[mi][ni][3])
                        : "r"(af[mi][0]), "r"(af[mi][1]), "r"(af[mi][2]), "r"(af[mi][3]),
                          "r"(bf[ni][0]), "r"(bf[ni][1]));
                }
        }
        __syncthreads();
    }

#pragma unroll
    for (int mi = 0; mi < 2; mi++)
#pragma unroll
        for (int ni = 0; ni < 8; ni++) {
            int r = row0 + wm + mi * 16 + gid;
            int cc = col0 + wn + ni * 8 + 2 * tig;
            float v0 = c[mi][ni][0], v1 = c[mi][ni][1];
            float v2 = c[mi][ni][2], v3 = c[mi][ni][3];
            if (bias) {
                float b0 = bias[cc], b1 = bias[cc + 1];
                v0 = __fadd_rn(v0, b0); v1 = __fadd_rn(v1, b1);
                v2 = __fadd_rn(v2, b0); v3 = __fadd_rn(v3, b1);
            }
            *reinterpret_cast<float2*>(&C[(size_t)r * ldC + cc])       = make_float2(v0, v1);
            *reinterpret_cast<float2*>(&C[(size_t)(r + 8) * ldC + cc]) = make_float2(v2, v3);
        }
}

// ---------------- weight / RoPE table prep ----------------
__global__ void build_wenc_kernel(const float* __restrict__ enc, const float* __restrict__ encv)
{
    int i = blockIdx.x * 256 + threadIdx.x;
    if (i >= DD * HH) return;
    int j = i % HH, d = i / HH;
    int h = j / HN, n = j % HN;
    size_t src = ((size_t)h * DD + d) * HN + n;
    g_We [i] = enc [src];
    g_Wev[i] = encv[src];
}

__global__ void build_rope_kernel()
{
    int i = blockIdx.x * 256 + threadIdx.x;
    if (i >= TT * HN) return;
    int n = i % HN, t = i / HN;
    float q   = floorf(__fdiv_rn((float)n, 2.0f)) * 2.0f;
    float ex  = __fdiv_rn(q, (float)HN);
    float tmp = powf(10000.0f, ex);
    float fr  = __fdiv_rn(1.0f, tmp);
    fr = __fdiv_rn(fr, 6.2831853071795862f);
    float ph  = __fmul_rn((float)t, fr);
    float frac = __fsub_rn(ph, truncf(ph));
    float ang = __fmul_rn(frac, 6.2831853071795862f);
    g_cos[i] = cosf(ang);
    g_sin[i] = sinf(ang);
}

// ---------------- embed + input layernorm ----------------
__global__ void embed_ln_kernel(const int* __restrict__ idx, const float* __restrict__ embed,
                                const float* __restrict__ w, const float* __restrict__ b)
{
    const int row = blockIdx.x;
    const int tok = idx[row];
    const float* e = embed + (size_t)tok * DD;
    __shared__ double shmd[32];
    float v[3]; double s = 0.0;
#pragma unroll
    for (int k = 0; k < 3; k++) { v[k] = e[threadIdx.x + k * 256]; s += (double)v[k]; }
    s = blockReduceSumD(s, shmd);
    float mu = __fdiv_rn((float)s, (float)DD);
    double ss = 0.0;
#pragma unroll
    for (int k = 0; k < 3; k++) { float d = __fsub_rn(v[k], mu); ss += (double)__fmul_rn(d, d); }
    ss = blockReduceSumD(ss, shmd);
    float var = __fdiv_rn((float)ss, (float)DD);
    float sd  = __fsqrt_rn(__fadd_rn(var, 1e-5f));
#pragma unroll
    for (int k = 0; k < 3; k++) {
        int j = threadIdx.x + k * 256;
        float norm = __fdiv_rn(__fsub_rn(v[k], mu), sd);
        g_x[(size_t)row * DD + j] = __fadd_rn(__fmul_rn(norm, w[j]), b[j]);
    }
}

// ---------------- layernorm + relu + exact kWTA + fused rope/transpose -------
// 512 threads. Double-reduction realization differs from 256-thread version
// only at the ~1e-16 level; LN with w=1 is monotone so kWTA ranking is
// unaffected — outputs match to final-ulp rounding of the same rn sequence.
__global__ __launch_bounds__(512) void ln_relu_kwta_kernel(
    const float* __restrict__ in,
    const float* __restrict__ w, const float* __restrict__ b,
    int ropeMode)
{
    __shared__ float sval[HH];            // 24 KB
    __shared__ unsigned int hist[256];
    __shared__ double shmd[32];
    __shared__ unsigned int s_prefix;
    __shared__ int s_k;

    const int row = blockIdx.x;
    const float* x = in + (size_t)row * HH;
    const int tid = threadIdx.x;          // 512 threads

    double s = 0.0;
    for (int j = tid; j < HH; j += 512) { float v = x[j]; sval[j] = v; s += (double)v; }
    s = blockReduceSumD(s, shmd);
    float mu = __fdiv_rn((float)s, (float)HH);
    double ss = 0.0;
    for (int j = tid; j < HH; j += 512) { float d = __fsub_rn(sval[j], mu); ss += (double)__fmul_rn(d, d); }
    ss = blockReduceSumD(ss, shmd);
    float var = __fdiv_rn((float)ss, (float)HH);
    float sd  = __fsqrt_rn(__fadd_rn(var, 1e-5f));

    for (int j = tid; j < HH; j += 512) {
        float norm = __fdiv_rn(__fsub_rn(sval[j], mu), sd);
        float v = __fadd_rn(__fmul_rn(norm, w[j]), b[j]);
        sval[j] = fmaxf(v, 0.f);
    }
    if (tid == 0) { s_prefix = 0u; s_k = KKEEP; }
    __syncthreads();

    for (int shift = 24; shift >= 0; shift -= 8) {
        if (tid < 256) hist[tid] = 0u;
        __syncthreads();
        unsigned int prefix = s_prefix;
        unsigned int maskhi = (shift == 24) ? 0u : (0xFFFFFFFFu << (shift + 8));
        for (int j = tid; j < HH; j += 512) {
            unsigned int bits = __float_as_uint(sval[j]);
            if ((bits & maskhi) == prefix)
                atomicAdd(&hist[(bits >> shift) & 0xFFu], 1u);
        }
        __syncthreads();
        if (tid == 0) {
            int k = s_k;
            unsigned int cum = 0; int bin = 255;
            for (; bin > 0; --bin) {
                unsigned int c = hist[bin];
                if (cum + c >= (unsigned)k) break;
                cum += c;
            }
            s_prefix = prefix | ((unsigned)bin << shift);
            s_k = k - (int)cum;
        }
        __syncthreads();
    }
    float thr = __uint_as_float(s_prefix);

    const int bb = row / TT, t = row % TT;
    if (ropeMode == 0) {
        for (int j = tid; j < HH; j += 512) {
            int n = j & (HN - 1), h = j >> 9;
            float qv = sval[j];      qv = (qv >= thr) ? qv : 0.f;
            float nb = (n & 1) ? sval[j - 1] : sval[j + 1];
            nb = (nb >= thr) ? nb : 0.f;
            float rot = (n & 1) ? nb : -nb;
            float c = g_cos[t * HN + n], sn = g_sin[t * HN + n];
            g_qr[(((size_t)bb * NHH + h) * TT + t) * HN + n] =
                __fadd_rn(__fmul_rn(qv, c), __fmul_rn(rot, sn));
        }
    } else {
        for (int j = tid; j < HH; j += 512) {
            int n = j & (HN - 1), h = j >> 9;
            float v = sval[j];
            g_vt[(((size_t)bb * NHH + h) * TT + t) * HN + n] = (v >= thr) ? v : 0.f;
        }
    }
}

// ---------------- causal softmax over rows (in place, 512 threads) -----------
__global__ __launch_bounds__(512) void softmax_kernel(float* __restrict__ att)
{
    const int gid = blockIdx.x;           // ((b*NH+h)*T + t)
    const int t = gid & (TT - 1);
    float* row = att + (size_t)gid * TT;
    __shared__ float shm[32];
    __shared__ double shmd[32];
    const int tid = threadIdx.x;
    const int n = t + 1;
    float m = -INFINITY;
    for (int j = tid; j < n; j += 512) m = fmaxf(m, row[j]);
    m = blockReduceMax(m, shm);
    double s = 0.0;
    for (int j = tid; j < n; j += 512) {
        float e = expf(__fsub_rn(row[j], m));
        row[j] = e;
        s += (double)e;
    }
    s = blockReduceSumD(s, shmd);
    float sf = (float)s;
    for (int j = tid; j < n; j += 512) row[j] = __fdiv_rn(row[j], sf);
    for (int j = n + tid; j < TT; j += 512) row[j] = 0.f;
}

// ---------------- residual + output layernorm ----------------
__global__ void residual_ln_kernel(const float* __restrict__ w, const float* __restrict__ b)
{
    const int row = blockIdx.x;
    const float* y = g_ydec + (size_t)row * DD;
    __shared__ double shmd[32];
    float v[3]; double s = 0.0;
#pragma unroll
    for (int k = 0; k < 3; k++) { v[k] = y[threadIdx.x + k * 256]; s += (double)v[k]; }
    s = blockReduceSumD(s, shmd);
    float mu = __fdiv_rn((float)s, (float)DD);
    double ss = 0.0;
#pragma unroll
    for (int k = 0; k < 3; k++) { float d = __fsub_rn(v[k], mu); ss += (double)__fmul_rn(d, d); }
    ss = blockReduceSumD(ss, shmd);
    float var = __fdiv_rn((float)ss, (float)DD);
    float sd  = __fsqrt_rn(__fadd_rn(var, 1e-5f));
#pragma unroll
    for (int k = 0; k < 3; k++) {
        int j = threadIdx.x + k * 256;
        float norm = __fdiv_rn(__fsub_rn(v[k], mu), sd);
        float ln = __fadd_rn(__fmul_rn(norm, w[j]), b[j]);
        g_x[(size_t)row * DD + j] = __fadd_rn(g_x[(size_t)row * DD + j], ln);
    }
}

// ---------------- host orchestration ----------------
extern "C" void kernel_launch(void* const* d_in, const int* in_sizes, int n_in,
                              void* d_out, int out_size)
{
    const int*   idx       = (const int*)  d_in[0];
    const float* embed_w   = (const float*)d_in[1];
    const float* ln_in_w   = (const float*)d_in[2];
    const float* ln_in_b   = (const float*)d_in[3];
    const float* encoder   = (const float*)d_in[4];
    const float* encoder_v = (const float*)d_in[5];
    const float* lnq_w     = (const float*)d_in[6];
    const float* lnq_b     = (const float*)d_in[7];
    const float* lnv_w     = (const float*)d_in[8];
    const float* lnv_b     = (const float*)d_in[9];
    const float* decoder_w = (const float*)d_in[10];
    const float* decoder_b = (const float*)d_in[11];
    const float* ln_out_w  = (const float*)d_in[12];
    const float* ln_out_b  = (const float*)d_in[13];
    const float* lm_head   = (const float*)d_in[14];
    float* out = (float*)d_out;

    float *p_x, *p_q, *p_v, *p_qr, *p_vt, *p_att, *p_ydec, *p_We, *p_Wev;
    cudaGetSymbolAddress((void**)&p_x,    g_x);
    cudaGetSymbolAddress((void**)&p_q,    g_q);
    cudaGetSymbolAddress((void**)&p_v,    g_v);
    cudaGetSymbolAddress((void**)&p_qr,   g_qr);
    cudaGetSymbolAddress((void**)&p_vt,   g_vt);
    cudaGetSymbolAddress((void**)&p_att,  g_att);
    cudaGetSymbolAddress((void**)&p_ydec, g_ydec);
    cudaGetSymbolAddress((void**)&p_We,   g_We);
    cudaGetSymbolAddress((void**)&p_Wev,  g_Wev);

    build_wenc_kernel<<<(DD * HH + 255) / 256, 256>>>(encoder, encoder_v);
    build_rope_kernel<<<(TT * HN + 255) / 256, 256>>>();
    embed_ln_kernel<<<NTOK, 256>>>(idx, embed_w, ln_in_w, ln_in_b);

    const float sqrt_n = 22.62741699796952f;  // fp32(sqrt(512))
    const long long sQR  = (long long)TT * HN;
    const long long sATT = (long long)TT * TT;

    for (int l = 0; l < LL; l++) {
        // encoders (frozen fp32 chunk numerics; feed kWTA)
        gemm_nn_chunk_kernel<<<dim3(HH / BN, NTOK / BM, 1), 64>>>(
            p_x, p_We,  p_q, nullptr, NTOK, HH, DD, 0, 0, 0, 0, 0);
        gemm_nn_chunk_kernel<<<dim3(HH / BN, NTOK / BM, 1), 64>>>(
            p_x, p_Wev, p_v, nullptr, NTOK, HH, DD, 0, 0, 0, 0, 0);

        // LN + relu + kWTA, fused rope/transpose outputs
        ln_relu_kwta_kernel<<<NTOK, 512>>>(p_q, lnq_w + (size_t)l * HH, lnq_b + (size_t)l * HH, 0);
        ln_relu_kwta_kernel<<<NTOK, 512>>>(p_v, lnv_w + (size_t)l * HH, lnv_b + (size_t)l * HH, 1);

        if (l < LL - 1) {
            // S = qr @ qr^T / sqrt(N) (frozen chunk numerics)
            gemm_nt_chunk_kernel<<<dim3(TT / BN, TT / BM, BB * NHH), 64>>>(
                p_qr, p_qr, p_att, TT, TT, HN, sqrt_n, sQR, sQR, sATT, 1);
            softmax_kernel<<<BB * NHH * TT, 512>>>(p_att);
            // Y = P @ V, written flat into g_q (no transpose pass)
            gemm_nn_chunk_kernel<<<dim3(HN / BN, TT / BM, BB * NHH), 64>>>(
                p_att, p_vt, p_q, nullptr, TT, HN, TT, sATT, sQR, 0, 1, 1);
            // y @ W_dec + b
            gemm_nn_chunk_kernel<<<dim3(DD / BN, NTOK / BM, 1), 64>>>(
                p_q, decoder_w, p_ydec, decoder_b, NTOK, DD, HH, 0, 0, 0, 0, 0);
        } else {
            // layer 3: everything downstream is smooth -> tf32 tensor cores
            tf32_nt_kernel<<<dim3(TT / LBN, TT / LBM, BB * NHH), 256>>>(
                p_qr, p_qr, p_att, TT, TT, HN, sqrt_n, 1, sQR, sQR, sATT, 1);
            softmax_kernel<<<BB * NHH * TT, 512>>>(p_att);
            tf32_nn_kernel<<<dim3(HN / LBN, TT / LBM, BB * NHH), 256>>>(
                p_att, p_vt, p_q, nullptr, TT, HN, TT, sATT, sQR, 0, 1, 1);
            tf32_nn_kernel<<<dim3(DD / LBN, NTOK / LBM, 1), 256>>>(
                p_q, decoder_w, p_ydec, decoder_b, NTOK, DD, HH, 0, 0, 0, 0, 0);
        }

        // x = residual + layernorm(y)
        residual_ln_kernel<<<NTOK, 256>>>(ln_out_w, ln_out_b);
    }

    // logits = x @ lm_head^T (tf32)
    tf32_nt_kernel<<<dim3(VOCABN / LBN, NTOK / LBM, 1), 256>>>(
        p_x, lm_head, out, NTOK, VOCABN, DD, 1.0f, 0, 0, 0, 0, 0);
}

// round 16
// speedup vs baseline: 1.0494x; 1.0494x over previous
#include <cuda_runtime.h>
#include <math.h>
#include <stdint.h>

// ---------------- problem constants ----------------
#define BB     2
#define TT     1024
#define DD     768
#define NHH    12
#define HN     512          // head dim N
#define HH     6144         // NH*N
#define LL     4
#define VOCABN 32000
#define KKEEP  921          // int(6144*0.15)
#define NTOK   (BB*TT)      // 2048

typedef unsigned long long ull;

// ---------------- packed f32x2 helpers (SASS FFMA2 path) ----------------
#define FMA2(d, a, b) \
    asm("fma.rn.f32x2 %0, %1, %2, %0;" : "+l"(d) : "l"(a), "l"(b))
#define ADD2(d, s) \
    asm("add.rn.f32x2 %0, %0, %1;" : "+l"(d) : "l"(s))
#define PACK_DUP(d, x) \
    asm("mov.b64 %0, {%1, %1};" : "=l"(d) : "f"(x))
#define UNPACK2(lo, hi, v) \
    asm("mov.b64 {%0, %1}, %2;" : "=f"(lo), "=f"(hi) : "l"(v))

// ---------------- scratch (device globals; no allocs allowed) ----------------
__device__ float g_x   [(size_t)NTOK*DD];
__device__ float g_q   [(size_t)NTOK*HH];   // encoder q out; later flat y
__device__ float g_v   [(size_t)NTOK*HH];   // encoder v out
__device__ float g_qr  [(size_t)BB*NHH*TT*HN];
__device__ float g_vt  [(size_t)BB*NHH*TT*HN];
__device__ float g_att [(size_t)BB*NHH*TT*TT];   // 100 MB scores/probs
__device__ float g_ydec[(size_t)NTOK*DD];
__device__ float g_We  [(size_t)DD*HH];
__device__ float g_Wev [(size_t)DD*HH];
__device__ float g_cos [(size_t)TT*HN];
__device__ float g_sin [(size_t)TT*HN];

// ---------------- reductions ----------------
__device__ __forceinline__ float warpReduceMax(float v){
#pragma unroll
    for (int o = 16; o > 0; o >>= 1) v = fmaxf(v, __shfl_down_sync(0xffffffffu, v, o));
    return v;
}
__device__ __forceinline__ double warpReduceSumD(double v){
#pragma unroll
    for (int o = 16; o > 0; o >>= 1) v += __shfl_down_sync(0xffffffffu, v, o);
    return v;
}
__device__ __forceinline__ double blockReduceSumD(double v, double* shm){
    int lane = threadIdx.x & 31, warp = threadIdx.x >> 5;
    v = warpReduceSumD(v);
    if (lane == 0) shm[warp] = v;
    __syncthreads();
    if (warp == 0) {
        v = (lane < ((blockDim.x + 31) >> 5)) ? shm[lane] : 0.0;
        v = warpReduceSumD(v);
        if (lane == 0) shm[0] = v;
    }
    __syncthreads();
    double r = shm[0];
    __syncthreads();
    return r;
}
__device__ __forceinline__ float blockReduceMax(float v, float* shm){
    int lane = threadIdx.x & 31, warp = threadIdx.x >> 5;
    v = warpReduceMax(v);
    if (lane == 0) shm[warp] = v;
    __syncthreads();
    if (warp == 0) {
        v = (lane < ((blockDim.x + 31) >> 5)) ? shm[lane] : -INFINITY;
        v = warpReduceMax(v);
        if (lane == 0) shm[0] = v;
    }
    __syncthreads();
    float r = shm[0];
    __syncthreads();
    return r;
}

// ---------------- fp32 chunk GEMMs (frozen numerics; layers 0-2 + encoders) --
// NUMERICS CONTRACT (R10): ascending k-chunks of 32; fresh-zero serial
// ascending FFMA(rn) chain per chunk; one rn merge per chunk. AT the scalar
// fp32 issue-rate roofline (~39 TF/s) — do not touch.
#define BM 64
#define BN 64
#define BK 32
#define GPAD 4

__global__ __launch_bounds__(64) void gemm_nn_chunk_kernel(
    const float* __restrict__ A, const float* __restrict__ B,
    float* __restrict__ C, const float* __restrict__ bias,
    int M, int N, int K,
    long long sA, long long sB, long long sC, int kLimit, int pvMode)
{
    const int z = blockIdx.z;
    A += (size_t)z * sA;
    B += (size_t)z * sB;
    int ldC = N;
    if (pvMode) { C += (size_t)(z / NHH) * TT * HH + (size_t)(z % NHH) * HN; ldC = HH; }
    else        { C += (size_t)z * sC; }
    const int bx = blockIdx.x, by = blockIdx.y;
    const int row0 = by * BM, col0 = bx * BN;
    __shared__ __align__(16) float As[BK][BM + GPAD];
    __shared__ __align__(16) float Bs[BK][BN + GPAD];
    const int tid = threadIdx.x;
    const int tx = tid & 7, ty = tid >> 3;
    ull acc2[8][4];
#pragma unroll
    for (int i = 0; i < 8; i++)
#pragma unroll
        for (int j = 0; j < 4; j++) acc2[i][j] = 0ULL;

    int kEnd = K;
    if (kLimit) { int lim = (by + 1) * BM; if (lim < kEnd) kEnd = lim; }

    for (int k0 = 0; k0 < kEnd; k0 += BK) {
#pragma unroll
        for (int e = tid; e < (BM * BK) / 4; e += 64) {
            int r = e >> 3, c4 = (e & 7) * 4;
            float4 v = *reinterpret_cast<const float4*>(&A[(size_t)(row0 + r) * K + k0 + c4]);
            As[c4 + 0][r] = v.x; As[c4 + 1][r] = v.y;
            As[c4 + 2][r] = v.z; As[c4 + 3][r] = v.w;
        }
#pragma unroll
        for (int e = tid; e < (BK * BN) / 4; e += 64) {
            int r = e >> 4, c4 = (e & 15) * 4;
            *reinterpret_cast<float4*>(&Bs[r][c4]) =
                *reinterpret_cast<const float4*>(&B[(size_t)(k0 + r) * N + col0 + c4]);
        }
        __syncthreads();

        ull s2[8][4];
#pragma unroll
        for (int i = 0; i < 8; i++)
#pragma unroll
            for (int j = 0; j < 4; j++) s2[i][j] = 0ULL;
#pragma unroll 4
        for (int kk = 0; kk < BK; kk++) {
            float a[8];
            *reinterpret_cast<float4*>(&a[0]) = *reinterpret_cast<const float4*>(&As[kk][ty * 8]);
            *reinterpret_cast<float4*>(&a[4]) = *reinterpret_cast<const float4*>(&As[kk][ty * 8 + 4]);
            const ull* brow = reinterpret_cast<const ull*>(&Bs[kk][tx * 8]);
            ull b2[4] = {brow[0], brow[1], brow[2], brow[3]};
            ull a2[8];
#pragma unroll
            for (int i = 0; i < 8; i++) PACK_DUP(a2[i], a[i]);
#pragma unroll
            for (int i = 0; i < 8; i++)
#pragma unroll
                for (int j = 0; j < 4; j++) FMA2(s2[i][j], a2[i], b2[j]);
        }
#pragma unroll
        for (int i = 0; i < 8; i++)
#pragma unroll
            for (int j = 0; j < 4; j++) ADD2(acc2[i][j], s2[i][j]);
        __syncthreads();
    }

    float bv[8];
#pragma unroll
    for (int j = 0; j < 8; j++) bv[j] = bias ? bias[col0 + tx * 8 + j] : 0.f;
#pragma unroll
    for (int i = 0; i < 8; i++) {
        float o[8];
#pragma unroll
        for (int j = 0; j < 4; j++) UNPACK2(o[2 * j], o[2 * j + 1], acc2[i][j]);
#pragma unroll
        for (int j = 0; j < 8; j++) o[j] = __fadd_rn(o[j], bv[j]);
        float* Crow = &C[(size_t)(row0 + ty * 8 + i) * ldC + col0 + tx * 8];
        *reinterpret_cast<float4*>(Crow)     = *reinterpret_cast<float4*>(&o[0]);
        *reinterpret_cast<float4*>(Crow + 4) = *reinterpret_cast<float4*>(&o[4]);
    }
}

__global__ __launch_bounds__(64) void gemm_nt_chunk_kernel(
    const float* __restrict__ A, const float* __restrict__ B,
    float* __restrict__ C,
    int M, int N, int K, float divisor,
    long long sA, long long sB, long long sC, int causal)
{
    const int bx = blockIdx.x, by = blockIdx.y;
    if (causal && bx > by) return;
    A += (size_t)blockIdx.z * sA;
    B += (size_t)blockIdx.z * sB;
    C += (size_t)blockIdx.z * sC;
    const int row0 = by * BM, col0 = bx * BN;
    __shared__ __align__(16) float As[BK][BM + GPAD];
    __shared__ __align__(16) float Bs[BK][BN + GPAD];
    const int tid = threadIdx.x;
    const int tx = tid & 7, ty = tid >> 3;
    ull acc2[8][4];
#pragma unroll
    for (int i = 0; i < 8; i++)
#pragma unroll
        for (int j = 0; j < 4; j++) acc2[i][j] = 0ULL;

    for (int k0 = 0; k0 < K; k0 += BK) {
#pragma unroll
        for (int e = tid; e < (BM * BK) / 4; e += 64) {
            int r = e >> 3, c4 = (e & 7) * 4;
            float4 v = *reinterpret_cast<const float4*>(&A[(size_t)(row0 + r) * K + k0 + c4]);
            As[c4 + 0][r] = v.x; As[c4 + 1][r] = v.y;
            As[c4 + 2][r] = v.z; As[c4 + 3][r] = v.w;
        }
#pragma unroll
        for (int e = tid; e < (BN * BK) / 4; e += 64) {
            int c = e >> 3, k4 = (e & 7) * 4;
            float4 v = *reinterpret_cast<const float4*>(&B[(size_t)(col0 + c) * K + k0 + k4]);
            Bs[k4 + 0][c] = v.x; Bs[k4 + 1][c] = v.y;
            Bs[k4 + 2][c] = v.z; Bs[k4 + 3][c] = v.w;
        }
        __syncthreads();

        ull s2[8][4];
#pragma unroll
        for (int i = 0; i < 8; i++)
#pragma unroll
            for (int j = 0; j < 4; j++) s2[i][j] = 0ULL;
#pragma unroll 4
        for (int kk = 0; kk < BK; kk++) {
            float a[8];
            *reinterpret_cast<float4*>(&a[0]) = *reinterpret_cast<const float4*>(&As[kk][ty * 8]);
            *reinterpret_cast<float4*>(&a[4]) = *reinterpret_cast<const float4*>(&As[kk][ty * 8 + 4]);
            const ull* brow = reinterpret_cast<const ull*>(&Bs[kk][tx * 8]);
            ull b2[4] = {brow[0], brow[1], brow[2], brow[3]};
            ull a2[8];
#pragma unroll
            for (int i = 0; i < 8; i++) PACK_DUP(a2[i], a[i]);
#pragma unroll
            for (int i = 0; i < 8; i++)
#pragma unroll
                for (int j = 0; j < 4; j++) FMA2(s2[i][j], a2[i], b2[j]);
        }
#pragma unroll
        for (int i = 0; i < 8; i++)
#pragma unroll
            for (int j = 0; j < 4; j++) ADD2(acc2[i][j], s2[i][j]);
        __syncthreads();
    }
#pragma unroll
    for (int i = 0; i < 8; i++) {
        float o[8];
#pragma unroll
        for (int j = 0; j < 4; j++) UNPACK2(o[2 * j], o[2 * j + 1], acc2[i][j]);
#pragma unroll
        for (int j = 0; j < 8; j++) o[j] = __fdiv_rn(o[j], divisor);
        float* Crow = &C[(size_t)(row0 + ty * 8 + i) * N + col0 + tx * 8];
        *reinterpret_cast<float4*>(Crow)     = *reinterpret_cast<float4*>(&o[0]);
        *reinterpret_cast<float4*>(Crow + 4) = *reinterpret_cast<float4*>(&o[4]);
    }
}

// ---------------- tf32 mma.sync GEMMs (smooth path: layer 3 attn + LM head) --
// R14 geometry (64x128 tile, 128 threads) with tf32 conversion hoisted to the
// smem fill (bit-identical: mma consumes the same rna-rounded values).
#define LBM 64
#define LBN 128
#define LBK 16
#define LPAD 8

__device__ __forceinline__ uint32_t f2tf32(float x){
    uint32_t u;
    asm("cvt.rna.tf32.f32 %0, %1;" : "=r"(u) : "f"(x));
    return u;
}

// C[M,N] = (A[M,K] * B[N,K]^T) (/divisor). causal: skip tiles above diagonal.
__global__ __launch_bounds__(128) void tf32_nt_kernel(
    const float* __restrict__ A, const float* __restrict__ B,
    float* __restrict__ C, int M, int N, int K,
    float divisor, int useDiv,
    long long sA, long long sB, long long sC, int causal)
{
    const int bx = blockIdx.x, by = blockIdx.y;
    const int row0 = by * LBM, col0 = bx * LBN;
    if (causal && col0 >= row0 + LBM) return;
    A += (size_t)blockIdx.z * sA;
    B += (size_t)blockIdx.z * sB;
    C += (size_t)blockIdx.z * sC;
    __shared__ __align__(16) uint32_t As[LBK][LBM + LPAD];
    __shared__ __align__(16) uint32_t Bs[LBK][LBN + LPAD];
    const int tid = threadIdx.x;
    const int warp = tid >> 5, lane = tid & 31;
    const int wm = (warp >> 1) * 32, wn = (warp & 1) * 64;
    const int gid = lane >> 2, tig = lane & 3;

    float c[2][8][4];
#pragma unroll
    for (int mi = 0; mi < 2; mi++)
#pragma unroll
        for (int ni = 0; ni < 8; ni++)
#pragma unroll
            for (int r = 0; r < 4; r++) c[mi][ni][r] = 0.f;

    for (int k0 = 0; k0 < K; k0 += LBK) {
#pragma unroll
        for (int e = tid; e < (LBM * LBK) / 4; e += 128) {
            int r = e >> 2, c4 = (e & 3) * 4;
            float4 v = *reinterpret_cast<const float4*>(&A[(size_t)(row0 + r) * K + k0 + c4]);
            As[c4 + 0][r] = f2tf32(v.x); As[c4 + 1][r] = f2tf32(v.y);
            As[c4 + 2][r] = f2tf32(v.z); As[c4 + 3][r] = f2tf32(v.w);
        }
#pragma unroll
        for (int e = tid; e < (LBN * LBK) / 4; e += 128) {
            int n = e >> 2, k4 = (e & 3) * 4;
            float4 v = *reinterpret_cast<const float4*>(&B[(size_t)(col0 + n) * K + k0 + k4]);
            Bs[k4 + 0][n] = f2tf32(v.x); Bs[k4 + 1][n] = f2tf32(v.y);
            Bs[k4 + 2][n] = f2tf32(v.z); Bs[k4 + 3][n] = f2tf32(v.w);
        }
        __syncthreads();

#pragma unroll
        for (int ks = 0; ks < LBK; ks += 8) {
            uint32_t af[2][4];
#pragma unroll
            for (int mi = 0; mi < 2; mi++) {
                int m0 = wm + mi * 16;
                af[mi][0] = As[ks + tig]    [m0 + gid];
                af[mi][1] = As[ks + tig]    [m0 + gid + 8];
                af[mi][2] = As[ks + tig + 4][m0 + gid];
                af[mi][3] = As[ks + tig + 4][m0 + gid + 8];
            }
            uint32_t bf[8][2];
#pragma unroll
            for (int ni = 0; ni < 8; ni++) {
                int n0 = wn + ni * 8;
                bf[ni][0] = Bs[ks + tig]    [n0 + gid];
                bf[ni][1] = Bs[ks + tig + 4][n0 + gid];
            }
#pragma unroll
            for (int mi = 0; mi < 2; mi++)
#pragma unroll
                for (int ni = 0; ni < 8; ni++) {
                    asm volatile(
                        "mma.sync.aligned.m16n8k8.row.col.f32.tf32.tf32.f32 "
                        "{%0,%1,%2,%3}, {%4,%5,%6,%7}, {%8,%9}, {%0,%1,%2,%3};"
                        : "+f"(c[mi][ni][0]), "+f"(c[mi][ni][1]),
                          "+f"(c[mi][ni][2]), "+f"(c[mi][ni][3])
                        : "r"(af[mi][0]), "r"(af[mi][1]), "r"(af[mi][2]), "r"(af[mi][3]),
                          "r"(bf[ni][0]), "r"(bf[ni][1]));
                }
        }
        __syncthreads();
    }

#pragma unroll
    for (int mi = 0; mi < 2; mi++)
#pragma unroll
        for (int ni = 0; ni < 8; ni++) {
            int r = row0 + wm + mi * 16 + gid;
            int cc = col0 + wn + ni * 8 + 2 * tig;
            float v0 = c[mi][ni][0], v1 = c[mi][ni][1];
            float v2 = c[mi][ni][2], v3 = c[mi][ni][3];
            if (useDiv) {
                v0 = __fdiv_rn(v0, divisor); v1 = __fdiv_rn(v1, divisor);
                v2 = __fdiv_rn(v2, divisor); v3 = __fdiv_rn(v3, divisor);
            }
            *reinterpret_cast<float2*>(&C[(size_t)r * N + cc])       = make_float2(v0, v1);
            *reinterpret_cast<float2*>(&C[(size_t)(r + 8) * N + cc]) = make_float2(v2, v3);
        }
}

// C[M,N] = A[M,K] * B[K,N] (+bias). kLimit: K limited to row0+LBM (causal PV).
// pvMode: flat attention-output write (ldC=HH).
__global__ __launch_bounds__(128) void tf32_nn_kernel(
    const float* __restrict__ A, const float* __restrict__ B,
    float* __restrict__ C, const float* __restrict__ bias,
    int M, int N, int K,
    long long sA, long long sB, long long sC, int kLimit, int pvMode)
{
    const int z = blockIdx.z;
    A += (size_t)z * sA;
    B += (size_t)z * sB;
    int ldC = N;
    if (pvMode) { C += (size_t)(z / NHH) * TT * HH + (size_t)(z % NHH) * HN; ldC = HH; }
    else        { C += (size_t)z * sC; }
    const int bx = blockIdx.x, by = blockIdx.y;
    const int row0 = by * LBM, col0 = bx * LBN;
    __shared__ __align__(16) uint32_t As[LBK][LBM + LPAD];
    __shared__ __align__(16) uint32_t Bs[LBK][LBN + LPAD];
    const int tid = threadIdx.x;
    const int warp = tid >> 5, lane = tid & 31;
    const int wm = (warp >> 1) * 32, wn = (warp & 1) * 64;
    const int gid = lane >> 2, tig = lane & 3;

    float c[2][8][4];
#pragma unroll
    for (int mi = 0; mi < 2; mi++)
#pragma unroll
        for (int ni = 0; ni < 8; ni++)
#pragma unroll
            for (int r = 0; r < 4; r++) c[mi][ni][r] = 0.f;

    int kEnd = K;
    if (kLimit) { int lim = row0 + LBM; if (lim < kEnd) kEnd = lim; }

    for (int k0 = 0; k0 < kEnd; k0 += LBK) {
#pragma unroll
        for (int e = tid; e < (LBM * LBK) / 4; e += 128) {
            int r = e >> 2, c4 = (e & 3) * 4;
            float4 v = *reinterpret_cast<const float4*>(&A[(size_t)(row0 + r) * K + k0 + c4]);
            As[c4 + 0][r] = f2tf32(v.x); As[c4 + 1][r] = f2tf32(v.y);
            As[c4 + 2][r] = f2tf32(v.z); As[c4 + 3][r] = f2tf32(v.w);
        }
#pragma unroll
        for (int e = tid; e < (LBK * LBN) / 4; e += 128) {
            int k = e >> 5, c4 = (e & 31) * 4;
            float4 v = *reinterpret_cast<const float4*>(&B[(size_t)(k0 + k) * N + col0 + c4]);
            Bs[k][c4 + 0] = f2tf32(v.x); Bs[k][c4 + 1] = f2tf32(v.y);
            Bs[k][c4 + 2] = f2tf32(v.z); Bs[k][c4 + 3] = f2tf32(v.w);
        }
        __syncthreads();

#pragma unroll
        for (int ks = 0; ks < LBK; ks += 8) {
            uint32_t af[2][4];
#pragma unroll
            for (int mi = 0; mi < 2; mi++) {
                int m0 = wm + mi * 16;
                af[mi][0] = As[ks + tig]    [m0 + gid];
                af[mi][1] = As[ks + tig]    [m0 + gid + 8];
                af[mi][2] = As[ks + tig + 4][m0 + gid];
                af[mi][3] = As[ks + tig + 4][m0 + gid + 8];
            }
            uint32_t bf[8][2];
#pragma unroll
            for (int ni = 0; ni < 8; ni++) {
                int n0 = wn + ni * 8;
                bf[ni][0] = Bs[ks + tig]    [n0 + gid];
                bf[ni][1] = Bs[ks + tig + 4][n0 + gid];
            }
#pragma unroll
            for (int mi = 0; mi < 2; mi++)
#pragma unroll
                for (int ni = 0; ni < 8; ni++) {
                    asm volatile(
                        "mma.sync.aligned.m16n8k8.row.col.f32.tf32.tf32.f32 "
                        "{%0,%1,%2,%3}, {%4,%5,%6,%7}, {%8,%9}, {%0,%1,%2,%3};"
                        : "+f"(c[mi][ni][0]), "+f"(c[mi][ni][1]),
                          "+f"(c[mi][ni][2]), "+f"(c[mi][ni][3])
                        : "r"(af[mi][0]), "r"(af[mi][1]), "r"(af[mi][2]), "r"(af[mi][3]),
                          "r"(bf[ni][0]), "r"(bf[ni][1]));
                }
        }
        __syncthreads();
    }

#pragma unroll
    for (int mi = 0; mi < 2; mi++)
#pragma unroll
        for (int ni = 0; ni < 8; ni++) {
            int r = row0 + wm + mi * 16 + gid;
            int cc = col0 + wn + ni * 8 + 2 * tig;
            float v0 = c[mi][ni][0], v1 = c[mi][ni][1];
            float v2 = c[mi][ni][2], v3 = c[mi][ni][3];
            if (bias) {
                float b0 = bias[cc], b1 = bias[cc + 1];
                v0 = __fadd_rn(v0, b0); v1 = __fadd_rn(v1, b1);
                v2 = __fadd_rn(v2, b0); v3 = __fadd_rn(v3, b1);
            }
            *reinterpret_cast<float2*>(&C[(size_t)r * ldC + cc])       = make_float2(v0, v1);
            *reinterpret_cast<float2*>(&C[(size_t)(r + 8) * ldC + cc]) = make_float2(v2, v3);
        }
}

// ---------------- weight / RoPE table prep ----------------
__global__ void build_wenc_kernel(const float* __restrict__ enc, const float* __restrict__ encv)
{
    int i = blockIdx.x * 256 + threadIdx.x;
    if (i >= DD * HH) return;
    int j = i % HH, d = i / HH;
    int h = j / HN, n = j % HN;
    size_t src = ((size_t)h * DD + d) * HN + n;
    g_We [i] = enc [src];
    g_Wev[i] = encv[src];
}

__global__ void build_rope_kernel()
{
    int i = blockIdx.x * 256 + threadIdx.x;
    if (i >= TT * HN) return;
    int n = i % HN, t = i / HN;
    float q   = floorf(__fdiv_rn((float)n, 2.0f)) * 2.0f;
    float ex  = __fdiv_rn(q, (float)HN);
    float tmp = powf(10000.0f, ex);
    float fr  = __fdiv_rn(1.0f, tmp);
    fr = __fdiv_rn(fr, 6.2831853071795862f);
    float ph  = __fmul_rn((float)t, fr);
    float frac = __fsub_rn(ph, truncf(ph));
    float ang = __fmul_rn(frac, 6.2831853071795862f);
    g_cos[i] = cosf(ang);
    g_sin[i] = sinf(ang);
}

// ---------------- embed + input layernorm ----------------
__global__ void embed_ln_kernel(const int* __restrict__ idx, const float* __restrict__ embed,
                                const float* __restrict__ w, const float* __restrict__ b)
{
    const int row = blockIdx.x;
    const int tok = idx[row];
    const float* e = embed + (size_t)tok * DD;
    __shared__ double shmd[32];
    float v[3]; double s = 0.0;
#pragma unroll
    for (int k = 0; k < 3; k++) { v[k] = e[threadIdx.x + k * 256]; s += (double)v[k]; }
    s = blockReduceSumD(s, shmd);
    float mu = __fdiv_rn((float)s, (float)DD);
    double ss = 0.0;
#pragma unroll
    for (int k = 0; k < 3; k++) { float d = __fsub_rn(v[k], mu); ss += (double)__fmul_rn(d, d); }
    ss = blockReduceSumD(ss, shmd);
    float var = __fdiv_rn((float)ss, (float)DD);
    float sd  = __fsqrt_rn(__fadd_rn(var, 1e-5f));
#pragma unroll
    for (int k = 0; k < 3; k++) {
        int j = threadIdx.x + k * 256;
        float norm = __fdiv_rn(__fsub_rn(v[k], mu), sd);
        g_x[(size_t)row * DD + j] = __fadd_rn(__fmul_rn(norm, w[j]), b[j]);
    }
}

// ---------------- layernorm + relu + exact kWTA + fused rope/transpose -------
__global__ void ln_relu_kwta_kernel(const float* __restrict__ in,
                                    const float* __restrict__ w, const float* __restrict__ b,
                                    int ropeMode)
{
    __shared__ float sval[HH];            // 24 KB
    __shared__ unsigned int hist[256];
    __shared__ double shmd[32];
    __shared__ unsigned int s_prefix;
    __shared__ int s_k;

    const int row = blockIdx.x;
    const float* x = in + (size_t)row * HH;
    const int tid = threadIdx.x;          // 256 threads

    double s = 0.0;
    for (int j = tid; j < HH; j += 256) { float v = x[j]; sval[j] = v; s += (double)v; }
    s = blockReduceSumD(s, shmd);
    float mu = __fdiv_rn((float)s, (float)HH);
    double ss = 0.0;
    for (int j = tid; j < HH; j += 256) { float d = __fsub_rn(sval[j], mu); ss += (double)__fmul_rn(d, d); }
    ss = blockReduceSumD(ss, shmd);
    float var = __fdiv_rn((float)ss, (float)HH);
    float sd  = __fsqrt_rn(__fadd_rn(var, 1e-5f));

    for (int j = tid; j < HH; j += 256) {
        float norm = __fdiv_rn(__fsub_rn(sval[j], mu), sd);
        float v = __fadd_rn(__fmul_rn(norm, w[j]), b[j]);
        sval[j] = fmaxf(v, 0.f);
    }
    if (tid == 0) { s_prefix = 0u; s_k = KKEEP; }
    __syncthreads();

    for (int shift = 24; shift >= 0; shift -= 8) {
        hist[tid] = 0u;
        __syncthreads();
        unsigned int prefix = s_prefix;
        unsigned int maskhi = (shift == 24) ? 0u : (0xFFFFFFFFu << (shift + 8));
        for (int j = tid; j < HH; j += 256) {
            unsigned int bits = __float_as_uint(sval[j]);
            if ((bits & maskhi) == prefix)
                atomicAdd(&hist[(bits >> shift) & 0xFFu], 1u);
        }
        __syncthreads();
        if (tid == 0) {
            int k = s_k;
            unsigned int cum = 0; int bin = 255;
            for (; bin > 0; --bin) {
                unsigned int c = hist[bin];
                if (cum + c >= (unsigned)k) break;
                cum += c;
            }
            s_prefix = prefix | ((unsigned)bin << shift);
            s_k = k - (int)cum;
        }
        __syncthreads();
    }
    float thr = __uint_as_float(s_prefix);

    const int bb = row / TT, t = row % TT;
    if (ropeMode == 0) {
        for (int j = tid; j < HH; j += 256) {
            int n = j & (HN - 1), h = j >> 9;
            float qv = sval[j];      qv = (qv >= thr) ? qv : 0.f;
            float nb = (n & 1) ? sval[j - 1] : sval[j + 1];
            nb = (nb >= thr) ? nb : 0.f;
            float rot = (n & 1) ? nb : -nb;
            float c = g_cos[t * HN + n], sn = g_sin[t * HN + n];
            g_qr[(((size_t)bb * NHH + h) * TT + t) * HN + n] =
                __fadd_rn(__fmul_rn(qv, c), __fmul_rn(rot, sn));
        }
    } else {
        for (int j = tid; j < HH; j += 256) {
            int n = j & (HN - 1), h = j >> 9;
            float v = sval[j];
            g_vt[(((size_t)bb * NHH + h) * TT + t) * HN + n] = (v >= thr) ? v : 0.f;
        }
    }
}

// ---------------- causal softmax over rows (in place) ----------------
__global__ void softmax_kernel(float* __restrict__ att)
{
    const int gid = blockIdx.x;           // ((b*NH+h)*T + t)
    const int t = gid & (TT - 1);
    float* row = att + (size_t)gid * TT;
    __shared__ float shm[32];
    __shared__ double shmd[32];
    const int tid = threadIdx.x;
    const int n = t + 1;
    float m = -INFINITY;
    for (int j = tid; j < n; j += 256) m = fmaxf(m, row[j]);
    m = blockReduceMax(m, shm);
    double s = 0.0;
    for (int j = tid; j < n; j += 256) {
        float e = expf(__fsub_rn(row[j], m));
        row[j] = e;
        s += (double)e;
    }
    s = blockReduceSumD(s, shmd);
    float sf = (float)s;
    for (int j = tid; j < n; j += 256) row[j] = __fdiv_rn(row[j], sf);
    for (int j = n + tid; j < TT; j += 256) row[j] = 0.f;
}

// ---------------- residual + output layernorm ----------------
__global__ void residual_ln_kernel(const float* __restrict__ w, const float* __restrict__ b)
{
    const int row = blockIdx.x;
    const float* y = g_ydec + (size_t)row * DD;
    __shared__ double shmd[32];
    float v[3]; double s = 0.0;
#pragma unroll
    for (int k = 0; k < 3; k++) { v[k] = y[threadIdx.x + k * 256]; s += (double)v[k]; }
    s = blockReduceSumD(s, shmd);
    float mu = __fdiv_rn((float)s, (float)DD);
    double ss = 0.0;
#pragma unroll
    for (int k = 0; k < 3; k++) { float d = __fsub_rn(v[k], mu); ss += (double)__fmul_rn(d, d); }
    ss = blockReduceSumD(ss, shmd);
    float var = __fdiv_rn((float)ss, (float)DD);
    float sd  = __fsqrt_rn(__fadd_rn(var, 1e-5f));
#pragma unroll
    for (int k = 0; k < 3; k++) {
        int j = threadIdx.x + k * 256;
        float norm = __fdiv_rn(__fsub_rn(v[k], mu), sd);
        float ln = __fadd_rn(__fmul_rn(norm, w[j]), b[j]);
        g_x[(size_t)row * DD + j] = __fadd_rn(g_x[(size_t)row * DD + j], ln);
    }
}

// ---------------- host orchestration ----------------
extern "C" void kernel_launch(void* const* d_in, const int* in_sizes, int n_in,
                              void* d_out, int out_size)
{
    const int*   idx       = (const int*)  d_in[0];
    const float* embed_w   = (const float*)d_in[1];
    const float* ln_in_w   = (const float*)d_in[2];
    const float* ln_in_b   = (const float*)d_in[3];
    const float* encoder   = (const float*)d_in[4];
    const float* encoder_v = (const float*)d_in[5];
    const float* lnq_w     = (const float*)d_in[6];
    const float* lnq_b     = (const float*)d_in[7];
    const float* lnv_w     = (const float*)d_in[8];
    const float* lnv_b     = (const float*)d_in[9];
    const float* decoder_w = (const float*)d_in[10];
    const float* decoder_b = (const float*)d_in[11];
    const float* ln_out_w  = (const float*)d_in[12];
    const float* ln_out_b  = (const float*)d_in[13];
    const float* lm_head   = (const float*)d_in[14];
    float* out = (float*)d_out;

    float *p_x, *p_q, *p_v, *p_qr, *p_vt, *p_att, *p_ydec, *p_We, *p_Wev;
    cudaGetSymbolAddress((void**)&p_x,    g_x);
    cudaGetSymbolAddress((void**)&p_q,    g_q);
    cudaGetSymbolAddress((void**)&p_v,    g_v);
    cudaGetSymbolAddress((void**)&p_qr,   g_qr);
    cudaGetSymbolAddress((void**)&p_vt,   g_vt);
    cudaGetSymbolAddress((void**)&p_att,  g_att);
    cudaGetSymbolAddress((void**)&p_ydec, g_ydec);
    cudaGetSymbolAddress((void**)&p_We,   g_We);
    cudaGetSymbolAddress((void**)&p_Wev,  g_Wev);

    build_wenc_kernel<<<(DD * HH + 255) / 256, 256>>>(encoder, encoder_v);
    build_rope_kernel<<<(TT * HN + 255) / 256, 256>>>();
    embed_ln_kernel<<<NTOK, 256>>>(idx, embed_w, ln_in_w, ln_in_b);

    const float sqrt_n = 22.62741699796952f;  // fp32(sqrt(512))
    const long long sQR  = (long long)TT * HN;
    const long long sATT = (long long)TT * TT;

    for (int l = 0; l < LL; l++) {
        // encoders (frozen fp32 chunk numerics; feed kWTA)
        gemm_nn_chunk_kernel<<<dim3(HH / BN, NTOK / BM, 1), 64>>>(
            p_x, p_We,  p_q, nullptr, NTOK, HH, DD, 0, 0, 0, 0, 0);
        gemm_nn_chunk_kernel<<<dim3(HH / BN, NTOK / BM, 1), 64>>>(
            p_x, p_Wev, p_v, nullptr, NTOK, HH, DD, 0, 0, 0, 0, 0);

        // LN + relu + kWTA, fused rope/transpose outputs
        ln_relu_kwta_kernel<<<NTOK, 256>>>(p_q, lnq_w + (size_t)l * HH, lnq_b + (size_t)l * HH, 0);
        ln_relu_kwta_kernel<<<NTOK, 256>>>(p_v, lnv_w + (size_t)l * HH, lnv_b + (size_t)l * HH, 1);

        if (l < LL - 1) {
            // S = qr @ qr^T / sqrt(N) (frozen chunk numerics)
            gemm_nt_chunk_kernel<<<dim3(TT / BN, TT / BM, BB * NHH), 64>>>(
                p_qr, p_qr, p_att, TT, TT, HN, sqrt_n, sQR, sQR, sATT, 1);
            softmax_kernel<<<BB * NHH * TT, 256>>>(p_att);
            // Y = P @ V, written flat into g_q (no transpose pass)
            gemm_nn_chunk_kernel<<<dim3(HN / BN, TT / BM, BB * NHH), 64>>>(
                p_att, p_vt, p_q, nullptr, TT, HN, TT, sATT, sQR, 0, 1, 1);
            // y @ W_dec + b
            gemm_nn_chunk_kernel<<<dim3(DD / BN, NTOK / BM, 1), 64>>>(
                p_q, decoder_w, p_ydec, decoder_b, NTOK, DD, HH, 0, 0, 0, 0, 0);
        } else {
            // layer 3: everything downstream is smooth -> tf32 tensor cores
            tf32_nt_kernel<<<dim3(TT / LBN, TT / LBM, BB * NHH), 128>>>(
                p_qr, p_qr, p_att, TT, TT, HN, sqrt_n, 1, sQR, sQR, sATT, 1);
            softmax_kernel<<<BB * NHH * TT, 256>>>(p_att);
            tf32_nn_kernel<<<dim3(HN / LBN, TT / LBM, BB * NHH), 128>>>(
                p_att, p_vt, p_q, nullptr, TT, HN, TT, sATT, sQR, 0, 1, 1);
            tf32_nn_kernel<<<dim3(DD / LBN, NTOK / LBM, 1), 128>>>(
                p_q, decoder_w, p_ydec, decoder_b, NTOK, DD, HH, 0, 0, 0, 0, 0);
        }

        // x = residual + layernorm(y)
        residual_ln_kernel<<<NTOK, 256>>>(ln_out_w, ln_out_b);
    }

    // logits = x @ lm_head^T (tf32)
    tf32_nt_kernel<<<dim3(VOCABN / LBN, NTOK / LBM, 1), 128>>>(
        p_x, lm_head, out, NTOK, VOCABN, DD, 1.0f, 0, 0, 0, 0, 0);
}